// round 11
// baseline (speedup 1.0000x reference)
#include <cuda_runtime.h>
#include <cuda.h>
#include <cstdint>
#include <cstddef>

#define N_ROWS 16384
#define K_TOT  16384
#define NCOL   128
#define BM     128
#define BK     32
#define KT     (K_TOT / BK)     // 512
#define NSTG   4

// k_big SMEM: 4 stages x 32KB (A 16KB: 128 rows x 128B | B 16KB: 128 cols x 128B)
#define STAGE_B   32768
#define B_OFF     16384
#define CTRL_OFF  (NSTG * STAGE_B)      // 131072
#define FULL_OFF  (CTRL_OFF)
#define SMEM_TOT  (CTRL_OFF + 64)
#define STAGE_TX  32768u

__device__ __align__(1024) float g_Tt[(size_t)NCOL * K_TOT];  // B^T: [128 cols][16384 k]
__device__ __align__(1024) float g_Y[(size_t)N_ROWS * NCOL];

__device__ __forceinline__ float elu_f(float x) { return x > 0.0f ? x : expm1f(x); }

__device__ __forceinline__ float round_tf32(float x) {
    uint32_t u;
    asm("cvt.rna.tf32.f32 %0, %1;" : "=r"(u) : "f"(x));
    return __uint_as_float(u);
}

__device__ __forceinline__ uint32_t smem_u32(const void* p) {
    uint32_t a;
    asm("{ .reg .u64 t; cvta.to.shared.u64 t, %1; cvt.u32.u64 %0, t; }" : "=r"(a) : "l"(p));
    return a;
}
__device__ __forceinline__ void mbar_init(uint32_t mbar, uint32_t cnt) {
    asm volatile("mbarrier.init.shared.b64 [%0], %1;" :: "r"(mbar), "r"(cnt) : "memory");
}
__device__ __forceinline__ void mbar_expect_tx(uint32_t mbar, uint32_t bytes) {
    asm volatile("mbarrier.arrive.expect_tx.shared.b64 _, [%0], %1;" :: "r"(mbar), "r"(bytes) : "memory");
}
__device__ __forceinline__ void mbar_wait(uint32_t mbar, uint32_t parity) {
    uint32_t done;
    asm volatile(
        "{\n\t.reg .pred p;\n\t"
        "mbarrier.try_wait.parity.acquire.cta.shared::cta.b64 p, [%1], %2;\n\t"
        "selp.b32 %0, 1, 0, p;\n\t}"
        : "=r"(done) : "r"(mbar), "r"(parity) : "memory");
    if (!done) {
        asm volatile(
            "{\n\t.reg .pred P1;\n\t"
            "WL_%=:\n\t"
            "mbarrier.try_wait.parity.acquire.cta.shared::cta.b64 P1, [%0], %1, 0x989680;\n\t"
            "@P1 bra.uni WD_%=;\n\t"
            "bra.uni WL_%=;\n\t"
            "WD_%=:\n\t}"
            :: "r"(mbar), "r"(parity) : "memory");
    }
}
__device__ __forceinline__ void tma2d(uint32_t dst, const CUtensorMap* tm,
                                      int x, int y, uint32_t mbar) {
    asm volatile(
        "cp.async.bulk.tensor.2d.shared::cta.global.tile.mbarrier::complete_tx::bytes "
        "[%0], [%1, {%2, %3}], [%4];"
        :: "r"(dst), "l"(tm), "r"(x), "r"(y), "r"(mbar) : "memory");
}

// ---------------------------------------------------------------------------
// k_pre: g_Tt[h*64+c][row] = sum_k elu(z[row, h*64+k]) * W0[k][c]  (transposed out)
// ---------------------------------------------------------------------------
__global__ void k_pre(const float* __restrict__ z, const float* __restrict__ W) {
    int h = blockIdx.y;
    int row0 = blockIdx.x * 64;
    __shared__ float xs[64][65];
    __shared__ float ws[64][65];
    int tid = threadIdx.x;
    for (int i = tid; i < 4096; i += 256) {
        int r = i >> 6, c = i & 63;
        xs[r][c] = elu_f(z[(size_t)(row0 + r) * 192 + h * 64 + c]);
        ws[r][c] = W[r * 64 + c];
    }
    __syncthreads();
    int tr = (tid >> 4) << 2, tc = (tid & 15) << 2;
    float acc[4][4] = {};
#pragma unroll 8
    for (int k = 0; k < 64; k++) {
        float xv[4], wv[4];
#pragma unroll
        for (int i = 0; i < 4; i++) xv[i] = xs[tr + i][k];
#pragma unroll
        for (int j = 0; j < 4; j++) wv[j] = ws[k][tc + j];
#pragma unroll
        for (int i = 0; i < 4; i++)
#pragma unroll
            for (int j = 0; j < 4; j++) acc[i][j] += xv[i] * wv[j];
    }
    __syncthreads();
#pragma unroll
    for (int i = 0; i < 4; i++)
#pragma unroll
        for (int j = 0; j < 4; j++)
            xs[tc + j][tr + i] = round_tf32(acc[i][j]);   // transpose in smem
    __syncthreads();
    for (int i = tid; i < 4096; i += 256) {
        int c = i >> 6, r = i & 63;
        g_Tt[(size_t)(h * 64 + c) * K_TOT + row0 + r] = xs[c][r];
    }
}

// ---------------------------------------------------------------------------
// k_mid: g_Tt[h*64+c][row] = sum_k Y[row, h*64+k] * W1[k][c]  (transposed out)
// ---------------------------------------------------------------------------
__global__ void k_mid(const float* __restrict__ W) {
    int h = blockIdx.y;
    int row0 = blockIdx.x * 64;
    __shared__ float xs[64][65];
    __shared__ float ws[64][65];
    int tid = threadIdx.x;
    for (int i = tid; i < 4096; i += 256) {
        int r = i >> 6, c = i & 63;
        xs[r][c] = g_Y[(size_t)(row0 + r) * NCOL + h * 64 + c];
        ws[r][c] = W[r * 64 + c];
    }
    __syncthreads();
    int tr = (tid >> 4) << 2, tc = (tid & 15) << 2;
    float acc[4][4] = {};
#pragma unroll 8
    for (int k = 0; k < 64; k++) {
        float xv[4], wv[4];
#pragma unroll
        for (int i = 0; i < 4; i++) xv[i] = xs[tr + i][k];
#pragma unroll
        for (int j = 0; j < 4; j++) wv[j] = ws[k][tc + j];
#pragma unroll
        for (int i = 0; i < 4; i++)
#pragma unroll
            for (int j = 0; j < 4; j++) acc[i][j] += xv[i] * wv[j];
    }
    __syncthreads();
#pragma unroll
    for (int i = 0; i < 4; i++)
#pragma unroll
        for (int j = 0; j < 4; j++)
            xs[tc + j][tr + i] = round_tf32(acc[i][j]);
    __syncthreads();
    for (int i = tid; i < 4096; i += 256) {
        int c = i >> 6, r = i & 63;
        g_Tt[(size_t)(h * 64 + c) * K_TOT + row0 + r] = xs[c][r];
    }
}

// ---------------------------------------------------------------------------
// k_final: out = [Y2_s | Y2_u | z_a] @ Wl + bl
// ---------------------------------------------------------------------------
__global__ void k_final(const float* __restrict__ z, const float* __restrict__ Wl,
                        const float* __restrict__ bl, float* __restrict__ out) {
    int row0 = blockIdx.x * 64;
    __shared__ float xs[64][65];
    __shared__ float ws[64][65];
    int tid = threadIdx.x;
    int tr = (tid >> 4) << 2, tc = (tid & 15) << 2;
    float acc[4][4] = {};
    for (int ch = 0; ch < 3; ch++) {
        __syncthreads();
        for (int i = tid; i < 4096; i += 256) {
            int r = i >> 6, c = i & 63;
            xs[r][c] = (ch < 2) ? g_Y[(size_t)(row0 + r) * NCOL + ch * 64 + c]
                                : z[(size_t)(row0 + r) * 192 + 128 + c];
            ws[r][c] = Wl[(ch * 64 + r) * 64 + c];
        }
        __syncthreads();
#pragma unroll 8
        for (int k = 0; k < 64; k++) {
            float xv[4], wv[4];
#pragma unroll
            for (int i = 0; i < 4; i++) xv[i] = xs[tr + i][k];
#pragma unroll
            for (int j = 0; j < 4; j++) wv[j] = ws[k][tc + j];
#pragma unroll
            for (int i = 0; i < 4; i++)
#pragma unroll
                for (int j = 0; j < 4; j++) acc[i][j] += xv[i] * wv[j];
        }
    }
#pragma unroll
    for (int i = 0; i < 4; i++)
#pragma unroll
        for (int j = 0; j < 4; j++)
            out[(size_t)(row0 + tr + i) * 64 + tc + j] = acc[i][j] + bl[tc + j];
}

// ---------------------------------------------------------------------------
// k_big: Y = elu(adj @ Tt^T + bias) — TMA tensor loads + mma.sync tf32
// 512 threads: 16 compute warps (4 M x 4 N) for latency hiding; thread 0 = producer.
// ---------------------------------------------------------------------------
__global__ void __launch_bounds__(512, 1) k_big(
    const __grid_constant__ CUtensorMap tmA,
    const __grid_constant__ CUtensorMap tmB,
    const float* __restrict__ bias)
{
    extern __shared__ __align__(1024) char smem[];
    uint32_t sb = smem_u32(smem);
    int tid = threadIdx.x;
    int lane = tid & 31, wid = tid >> 5;
    int wm = wid & 3, wn = wid >> 2;                  // 4 M-groups x 4 N-groups
    int m0 = blockIdx.x * BM;

    if (tid == 0) {
#pragma unroll
        for (int s = 0; s < NSTG; s++) mbar_init(sb + FULL_OFF + s * 8, 1);
    }
    __syncthreads();
    if (tid == 0) {
#pragma unroll
        for (int s = 0; s < NSTG; s++) {
            mbar_expect_tx(sb + FULL_OFF + s * 8, STAGE_TX);
            tma2d(sb + s * STAGE_B,         &tmA, s * BK, m0, sb + FULL_OFF + s * 8);
            tma2d(sb + s * STAGE_B + B_OFF, &tmB, s * BK, 0,  sb + FULL_OFF + s * 8);
        }
    }

    float acc[2][4][4];
#pragma unroll
    for (int t = 0; t < 2; t++)
#pragma unroll
        for (int j = 0; j < 4; j++)
#pragma unroll
            for (int q = 0; q < 4; q++) acc[t][j][q] = 0.0f;

    // per-thread invariants for swizzled fragment addressing
    const uint32_t lane4 = (lane & 3) * 4;            // k sub-offset bytes
    const uint32_t xorv  = (lane >> 2) << 4;          // SW128 XOR: (row&7)<<4, row&7 == lane>>2
    const int rA = wm * 32 + (lane >> 2);             // A fragment base row (t*16 added below)
    const int cB = wn * 32 + (lane >> 2);             // B fragment base col (j*8 added below)

    for (int kt = 0; kt < KT; kt++) {
        int s = kt & (NSTG - 1);
        mbar_wait(sb + FULL_OFF + s * 8, (kt >> 2) & 1);
        const char* sa = smem + s * STAGE_B;
        const char* sbu = smem + s * STAGE_B + B_OFF;

#pragma unroll
        for (int kk = 0; kk < 4; kk++) {
            uint32_t kcb = kk * 32 + lane4;           // byte offset of k within 128B row
            uint32_t v0 = kcb ^ xorv;
            uint32_t v2 = (kcb + 16) ^ xorv;

            uint32_t a[2][4];
#pragma unroll
            for (int t = 0; t < 2; t++) {
                uint32_t base = (uint32_t)(rA + t * 16) * 128;
                a[t][0] = __float_as_uint(round_tf32(*(const float*)(sa + base + v0)));
                a[t][1] = __float_as_uint(round_tf32(*(const float*)(sa + base + 1024 + v0)));
                a[t][2] = __float_as_uint(round_tf32(*(const float*)(sa + base + v2)));
                a[t][3] = __float_as_uint(round_tf32(*(const float*)(sa + base + 1024 + v2)));
            }
            uint32_t offb0 = (uint32_t)cB * 128 + v0;
            uint32_t offb1 = (uint32_t)cB * 128 + v2;
#pragma unroll
            for (int j = 0; j < 4; j++) {
                uint32_t b0 = *(const uint32_t*)(sbu + offb0 + (uint32_t)j * 1024);
                uint32_t b1 = *(const uint32_t*)(sbu + offb1 + (uint32_t)j * 1024);
#pragma unroll
                for (int t = 0; t < 2; t++) {
                    asm volatile(
                        "mma.sync.aligned.m16n8k8.row.col.f32.tf32.tf32.f32 "
                        "{%0,%1,%2,%3}, {%4,%5,%6,%7}, {%8,%9}, {%0,%1,%2,%3};"
                        : "+f"(acc[t][j][0]), "+f"(acc[t][j][1]),
                          "+f"(acc[t][j][2]), "+f"(acc[t][j][3])
                        : "r"(a[t][0]), "r"(a[t][1]), "r"(a[t][2]), "r"(a[t][3]),
                          "r"(b0), "r"(b1));
                }
            }
        }
        __syncthreads();                              // all warps done with slot s
        int nk = kt + NSTG;
        if (tid == 0 && nk < KT) {
            mbar_expect_tx(sb + FULL_OFF + s * 8, STAGE_TX);
            tma2d(sb + s * STAGE_B,         &tmA, nk * BK, m0, sb + FULL_OFF + s * 8);
            tma2d(sb + s * STAGE_B + B_OFF, &tmB, nk * BK, 0,  sb + FULL_OFF + s * 8);
        }
    }

    // Epilogue: + bias (per-64 broadcast), elu, store fp32
#pragma unroll
    for (int t = 0; t < 2; t++) {
#pragma unroll
        for (int j = 0; j < 4; j++) {
            int r = m0 + wm * 32 + t * 16 + (lane >> 2);
            int c = wn * 32 + j * 8 + ((lane & 3) << 1);
            float b0 = bias[c & 63];
            float b1 = bias[(c + 1) & 63];
            g_Y[(size_t)r * NCOL + c]           = elu_f(acc[t][j][0] + b0);
            g_Y[(size_t)r * NCOL + c + 1]       = elu_f(acc[t][j][1] + b1);
            g_Y[(size_t)(r + 8) * NCOL + c]     = elu_f(acc[t][j][2] + b0);
            g_Y[(size_t)(r + 8) * NCOL + c + 1] = elu_f(acc[t][j][3] + b1);
        }
    }
}

// ---------------------------------------------------------------------------
typedef CUresult (*EncodeFn)(CUtensorMap*, CUtensorMapDataType, cuuint32_t, void*,
                             const cuuint64_t*, const cuuint64_t*, const cuuint32_t*,
                             const cuuint32_t*, CUtensorMapInterleave, CUtensorMapSwizzle,
                             CUtensorMapL2promotion, CUtensorMapFloatOOBfill);

static void make_map(EncodeFn enc, CUtensorMap* tm, const void* base,
                     uint64_t d0, uint64_t d1) {
    cuuint64_t dims[2] = {d0, d1};
    cuuint64_t strides[1] = {d0 * 4};
    cuuint32_t box[2] = {32, 128};      // 32 floats (128B) x 128 rows, SW128
    cuuint32_t es[2] = {1, 1};
    enc(tm, CU_TENSOR_MAP_DATA_TYPE_FLOAT32, 2, (void*)base, dims, strides, box, es,
        CU_TENSOR_MAP_INTERLEAVE_NONE, CU_TENSOR_MAP_SWIZZLE_128B,
        CU_TENSOR_MAP_L2_PROMOTION_L2_128B, CU_TENSOR_MAP_FLOAT_OOB_FILL_NONE);
}

extern "C" void kernel_launch(void* const* d_in, const int* in_sizes, int n_in,
                              void* d_out, int out_size) {
    const float *z = nullptr, *adj = nullptr, *Ws = nullptr, *bs = nullptr,
                *Wl = nullptr, *bl = nullptr;
    for (int i = 0; i < n_in; i++) {
        switch (in_sizes[i]) {
            case 16384 * 192:  z   = (const float*)d_in[i]; break;
            case 268435456:    adj = (const float*)d_in[i]; break;
            case 8192:         Ws  = (const float*)d_in[i]; break;
            case 128:          bs  = (const float*)d_in[i]; break;
            case 12288:        Wl  = (const float*)d_in[i]; break;
            case 64:           bl  = (const float*)d_in[i]; break;
            default: break;
        }
    }
    float* out = (float*)d_out;

    static EncodeFn enc = nullptr;
    if (!enc) {
        void* p = nullptr;
        cudaDriverEntryPointQueryResult qr;
        cudaGetDriverEntryPointByVersion("cuTensorMapEncodeTiled", &p, 12050,
                                         cudaEnableDefault, &qr);
        enc = (EncodeFn)p;
        cudaFuncSetAttribute(k_big, cudaFuncAttributeMaxDynamicSharedMemorySize, SMEM_TOT);
    }

    void* ttp = nullptr;
    cudaGetSymbolAddress(&ttp, g_Tt);

    CUtensorMap tmA, tmB;
    make_map(enc, &tmA, adj, K_TOT, N_ROWS);   // adj: [16384 m][16384 k]
    make_map(enc, &tmB, ttp, K_TOT, NCOL);     // g_Tt: [128 c][16384 k]

    k_pre<<<dim3(256, 2), 256>>>(z, Ws);
    k_big<<<128, 512, SMEM_TOT>>>(tmA, tmB, bs);
    k_mid<<<dim3(256, 2), 256>>>(Ws + 4096);
    k_big<<<128, 512, SMEM_TOT>>>(tmA, tmB, bs + 64);
    k_final<<<256, 256>>>(z, Wl, bl, out);
}

// round 13
// speedup vs baseline: 1.0310x; 1.0310x over previous
#include <cuda_runtime.h>
#include <cuda.h>
#include <cstdint>
#include <cstddef>

#define N_ROWS 16384
#define K_TOT  16384
#define NCOL   128
#define BM     128
#define BK     32
#define KT     (K_TOT / BK)     // 512
#define NSTG   4

// k_big SMEM: 4 stages x 32KB (A 16KB: 128 rows x 128B | B 16KB: 128 cols x 128B)
#define STAGE_B   32768
#define B_OFF     16384
#define CTRL_OFF  (NSTG * STAGE_B)      // 131072
#define FULL_OFF  (CTRL_OFF)            // 4 x 8B
#define EMPTY_OFF (CTRL_OFF + 32)       // 4 x 8B
#define SMEM_TOT  (CTRL_OFF + 96)
#define STAGE_TX  32768u

__device__ __align__(1024) float g_Tt[(size_t)NCOL * K_TOT];  // B^T: [128 cols][16384 k]
__device__ __align__(1024) float g_Y[(size_t)N_ROWS * NCOL];

__device__ __forceinline__ float elu_f(float x) { return x > 0.0f ? x : expm1f(x); }

__device__ __forceinline__ float round_tf32(float x) {
    uint32_t u;
    asm("cvt.rna.tf32.f32 %0, %1;" : "=r"(u) : "f"(x));
    return __uint_as_float(u);
}

__device__ __forceinline__ uint32_t smem_u32(const void* p) {
    uint32_t a;
    asm("{ .reg .u64 t; cvta.to.shared.u64 t, %1; cvt.u32.u64 %0, t; }" : "=r"(a) : "l"(p));
    return a;
}
__device__ __forceinline__ void mbar_init(uint32_t mbar, uint32_t cnt) {
    asm volatile("mbarrier.init.shared.b64 [%0], %1;" :: "r"(mbar), "r"(cnt) : "memory");
}
__device__ __forceinline__ void mbar_expect_tx(uint32_t mbar, uint32_t bytes) {
    asm volatile("mbarrier.arrive.expect_tx.shared.b64 _, [%0], %1;" :: "r"(mbar), "r"(bytes) : "memory");
}
__device__ __forceinline__ void mbar_arrive(uint32_t mbar) {
    asm volatile("mbarrier.arrive.shared.b64 _, [%0];" :: "r"(mbar) : "memory");
}
__device__ __forceinline__ void mbar_wait(uint32_t mbar, uint32_t parity) {
    uint32_t done;
    asm volatile(
        "{\n\t.reg .pred p;\n\t"
        "mbarrier.try_wait.parity.acquire.cta.shared::cta.b64 p, [%1], %2;\n\t"
        "selp.b32 %0, 1, 0, p;\n\t}"
        : "=r"(done) : "r"(mbar), "r"(parity) : "memory");
    if (!done) {
        asm volatile(
            "{\n\t.reg .pred P1;\n\t"
            "WL_%=:\n\t"
            "mbarrier.try_wait.parity.acquire.cta.shared::cta.b64 P1, [%0], %1, 0x989680;\n\t"
            "@P1 bra.uni WD_%=;\n\t"
            "bra.uni WL_%=;\n\t"
            "WD_%=:\n\t}"
            :: "r"(mbar), "r"(parity) : "memory");
    }
}
__device__ __forceinline__ void tma2d(uint32_t dst, const CUtensorMap* tm,
                                      int x, int y, uint32_t mbar) {
    asm volatile(
        "cp.async.bulk.tensor.2d.shared::cta.global.tile.mbarrier::complete_tx::bytes "
        "[%0], [%1, {%2, %3}], [%4];"
        :: "r"(dst), "l"(tm), "r"(x), "r"(y), "r"(mbar) : "memory");
}

// ---------------------------------------------------------------------------
// k_pre: g_Tt[h*64+c][row] = sum_k elu(z[row, h*64+k]) * W0[k][c]  (transposed out)
// ---------------------------------------------------------------------------
__global__ void k_pre(const float* __restrict__ z, const float* __restrict__ W) {
    int h = blockIdx.y;
    int row0 = blockIdx.x * 64;
    __shared__ float xs[64][65];
    __shared__ float ws[64][65];
    int tid = threadIdx.x;
    for (int i = tid; i < 4096; i += 256) {
        int r = i >> 6, c = i & 63;
        xs[r][c] = elu_f(z[(size_t)(row0 + r) * 192 + h * 64 + c]);
        ws[r][c] = W[r * 64 + c];
    }
    __syncthreads();
    int tr = (tid >> 4) << 2, tc = (tid & 15) << 2;
    float acc[4][4] = {};
#pragma unroll 8
    for (int k = 0; k < 64; k++) {
        float xv[4], wv[4];
#pragma unroll
        for (int i = 0; i < 4; i++) xv[i] = xs[tr + i][k];
#pragma unroll
        for (int j = 0; j < 4; j++) wv[j] = ws[k][tc + j];
#pragma unroll
        for (int i = 0; i < 4; i++)
#pragma unroll
            for (int j = 0; j < 4; j++) acc[i][j] += xv[i] * wv[j];
    }
    __syncthreads();
#pragma unroll
    for (int i = 0; i < 4; i++)
#pragma unroll
        for (int j = 0; j < 4; j++)
            xs[tc + j][tr + i] = round_tf32(acc[i][j]);   // transpose in smem
    __syncthreads();
    for (int i = tid; i < 4096; i += 256) {
        int c = i >> 6, r = i & 63;
        g_Tt[(size_t)(h * 64 + c) * K_TOT + row0 + r] = xs[c][r];
    }
}

// ---------------------------------------------------------------------------
// k_mid: g_Tt[h*64+c][row] = sum_k Y[row, h*64+k] * W1[k][c]  (transposed out)
// ---------------------------------------------------------------------------
__global__ void k_mid(const float* __restrict__ W) {
    int h = blockIdx.y;
    int row0 = blockIdx.x * 64;
    __shared__ float xs[64][65];
    __shared__ float ws[64][65];
    int tid = threadIdx.x;
    for (int i = tid; i < 4096; i += 256) {
        int r = i >> 6, c = i & 63;
        xs[r][c] = g_Y[(size_t)(row0 + r) * NCOL + h * 64 + c];
        ws[r][c] = W[r * 64 + c];
    }
    __syncthreads();
    int tr = (tid >> 4) << 2, tc = (tid & 15) << 2;
    float acc[4][4] = {};
#pragma unroll 8
    for (int k = 0; k < 64; k++) {
        float xv[4], wv[4];
#pragma unroll
        for (int i = 0; i < 4; i++) xv[i] = xs[tr + i][k];
#pragma unroll
        for (int j = 0; j < 4; j++) wv[j] = ws[k][tc + j];
#pragma unroll
        for (int i = 0; i < 4; i++)
#pragma unroll
            for (int j = 0; j < 4; j++) acc[i][j] += xv[i] * wv[j];
    }
    __syncthreads();
#pragma unroll
    for (int i = 0; i < 4; i++)
#pragma unroll
        for (int j = 0; j < 4; j++)
            xs[tc + j][tr + i] = round_tf32(acc[i][j]);
    __syncthreads();
    for (int i = tid; i < 4096; i += 256) {
        int c = i >> 6, r = i & 63;
        g_Tt[(size_t)(h * 64 + c) * K_TOT + row0 + r] = xs[c][r];
    }
}

// ---------------------------------------------------------------------------
// k_final: out = [Y2_s | Y2_u | z_a] @ Wl + bl
// ---------------------------------------------------------------------------
__global__ void k_final(const float* __restrict__ z, const float* __restrict__ Wl,
                        const float* __restrict__ bl, float* __restrict__ out) {
    int row0 = blockIdx.x * 64;
    __shared__ float xs[64][65];
    __shared__ float ws[64][65];
    int tid = threadIdx.x;
    int tr = (tid >> 4) << 2, tc = (tid & 15) << 2;
    float acc[4][4] = {};
    for (int ch = 0; ch < 3; ch++) {
        __syncthreads();
        for (int i = tid; i < 4096; i += 256) {
            int r = i >> 6, c = i & 63;
            xs[r][c] = (ch < 2) ? g_Y[(size_t)(row0 + r) * NCOL + ch * 64 + c]
                                : z[(size_t)(row0 + r) * 192 + 128 + c];
            ws[r][c] = Wl[(ch * 64 + r) * 64 + c];
        }
        __syncthreads();
#pragma unroll 8
        for (int k = 0; k < 64; k++) {
            float xv[4], wv[4];
#pragma unroll
            for (int i = 0; i < 4; i++) xv[i] = xs[tr + i][k];
#pragma unroll
            for (int j = 0; j < 4; j++) wv[j] = ws[k][tc + j];
#pragma unroll
            for (int i = 0; i < 4; i++)
#pragma unroll
                for (int j = 0; j < 4; j++) acc[i][j] += xv[i] * wv[j];
        }
    }
#pragma unroll
    for (int i = 0; i < 4; i++)
#pragma unroll
        for (int j = 0; j < 4; j++)
            out[(size_t)(row0 + tr + i) * 64 + tc + j] = acc[i][j] + bl[tc + j];
}

// ---------------------------------------------------------------------------
// k_big: Y = elu(adj @ Tt^T + bias) — TMA tensor loads + mma.sync tf32
// 256 threads (8 warps, 4M x 2N). No per-ktile __syncthreads: per-slot empty
// mbarriers (arrive-count 256) let warps skew across ktiles; thread 0 waits
// empty[s] before re-issuing TMA into slot s.
// ---------------------------------------------------------------------------
__global__ void __launch_bounds__(256, 1) k_big(
    const __grid_constant__ CUtensorMap tmA,
    const __grid_constant__ CUtensorMap tmB,
    const float* __restrict__ bias)
{
    extern __shared__ __align__(1024) char smem[];
    uint32_t sb = smem_u32(smem);
    int tid = threadIdx.x;
    int lane = tid & 31, wid = tid >> 5;
    int wm = wid & 3, wn = wid >> 2;                  // 4 M-groups x 2 N-groups
    int m0 = blockIdx.x * BM;

    if (tid == 0) {
#pragma unroll
        for (int s = 0; s < NSTG; s++) {
            mbar_init(sb + FULL_OFF + s * 8, 1);
            mbar_init(sb + EMPTY_OFF + s * 8, 256);
        }
    }
    __syncthreads();
    if (tid == 0) {
#pragma unroll
        for (int s = 0; s < NSTG; s++) {
            mbar_expect_tx(sb + FULL_OFF + s * 8, STAGE_TX);
            tma2d(sb + s * STAGE_B,         &tmA, s * BK, m0, sb + FULL_OFF + s * 8);
            tma2d(sb + s * STAGE_B + B_OFF, &tmB, s * BK, 0,  sb + FULL_OFF + s * 8);
        }
    }

    float acc[2][8][4];
#pragma unroll
    for (int t = 0; t < 2; t++)
#pragma unroll
        for (int j = 0; j < 8; j++)
#pragma unroll
            for (int q = 0; q < 4; q++) acc[t][j][q] = 0.0f;

    // per-thread invariants for swizzled fragment addressing
    const uint32_t lane4 = (lane & 3) * 4;            // k sub-offset bytes
    const uint32_t xorv  = (lane >> 2) << 4;          // SW128 XOR: (row&7)<<4, row&7 == lane>>2
    const int rA = wm * 32 + (lane >> 2);             // A fragment base row
    const int cB = wn * 64 + (lane >> 2);             // B fragment base col

    uint32_t phe = 0;                                 // thread 0: empty-phase per round

    for (int kt = 0; kt < KT; kt++) {
        int s = kt & (NSTG - 1);
        mbar_wait(sb + FULL_OFF + s * 8, (kt >> 2) & 1);
        const char* sa = smem + s * STAGE_B;
        const char* sbu = smem + s * STAGE_B + B_OFF;

#pragma unroll
        for (int kk = 0; kk < 4; kk++) {
            uint32_t kcb = kk * 32 + lane4;           // byte offset of k within 128B row
            uint32_t v0 = kcb ^ xorv;
            uint32_t v2 = (kcb + 16) ^ xorv;

            uint32_t a[2][4];
#pragma unroll
            for (int t = 0; t < 2; t++) {
                uint32_t base = (uint32_t)(rA + t * 16) * 128;
                a[t][0] = __float_as_uint(round_tf32(*(const float*)(sa + base + v0)));
                a[t][1] = __float_as_uint(round_tf32(*(const float*)(sa + base + 1024 + v0)));
                a[t][2] = __float_as_uint(round_tf32(*(const float*)(sa + base + v2)));
                a[t][3] = __float_as_uint(round_tf32(*(const float*)(sa + base + 1024 + v2)));
            }
            uint32_t offb0 = (uint32_t)cB * 128 + v0;
            uint32_t offb1 = (uint32_t)cB * 128 + v2;
#pragma unroll
            for (int j = 0; j < 8; j++) {
                uint32_t b0 = *(const uint32_t*)(sbu + offb0 + (uint32_t)j * 1024);
                uint32_t b1 = *(const uint32_t*)(sbu + offb1 + (uint32_t)j * 1024);
#pragma unroll
                for (int t = 0; t < 2; t++) {
                    asm volatile(
                        "mma.sync.aligned.m16n8k8.row.col.f32.tf32.tf32.f32 "
                        "{%0,%1,%2,%3}, {%4,%5,%6,%7}, {%8,%9}, {%0,%1,%2,%3};"
                        : "+f"(acc[t][j][0]), "+f"(acc[t][j][1]),
                          "+f"(acc[t][j][2]), "+f"(acc[t][j][3])
                        : "r"(a[t][0]), "r"(a[t][1]), "r"(a[t][2]), "r"(a[t][3]),
                          "r"(b0), "r"(b1));
                }
            }
        }

        mbar_arrive(sb + EMPTY_OFF + s * 8);          // this thread done with slot s
        int nk = kt + NSTG;
        if (tid == 0 && nk < KT) {
            mbar_wait(sb + EMPTY_OFF + s * 8, phe & 1);   // all 256 done with slot s
            if (s == NSTG - 1) phe++;                      // one phase per full round
            mbar_expect_tx(sb + FULL_OFF + s * 8, STAGE_TX);
            tma2d(sb + s * STAGE_B,         &tmA, nk * BK, m0, sb + FULL_OFF + s * 8);
            tma2d(sb + s * STAGE_B + B_OFF, &tmB, nk * BK, 0,  sb + FULL_OFF + s * 8);
        }
    }

    // Epilogue: + bias (per-64 broadcast), elu, store fp32
#pragma unroll
    for (int t = 0; t < 2; t++) {
#pragma unroll
        for (int j = 0; j < 8; j++) {
            int r = m0 + wm * 32 + t * 16 + (lane >> 2);
            int c = wn * 64 + j * 8 + ((lane & 3) << 1);
            float b0 = bias[c & 63];
            float b1 = bias[(c + 1) & 63];
            g_Y[(size_t)r * NCOL + c]           = elu_f(acc[t][j][0] + b0);
            g_Y[(size_t)r * NCOL + c + 1]       = elu_f(acc[t][j][1] + b1);
            g_Y[(size_t)(r + 8) * NCOL + c]     = elu_f(acc[t][j][2] + b0);
            g_Y[(size_t)(r + 8) * NCOL + c + 1] = elu_f(acc[t][j][3] + b1);
        }
    }
}

// ---------------------------------------------------------------------------
typedef CUresult (*EncodeFn)(CUtensorMap*, CUtensorMapDataType, cuuint32_t, void*,
                             const cuuint64_t*, const cuuint64_t*, const cuuint32_t*,
                             const cuuint32_t*, CUtensorMapInterleave, CUtensorMapSwizzle,
                             CUtensorMapL2promotion, CUtensorMapFloatOOBfill);

static void make_map(EncodeFn enc, CUtensorMap* tm, const void* base,
                     uint64_t d0, uint64_t d1) {
    cuuint64_t dims[2] = {d0, d1};
    cuuint64_t strides[1] = {d0 * 4};
    cuuint32_t box[2] = {32, 128};      // 32 floats (128B) x 128 rows, SW128
    cuuint32_t es[2] = {1, 1};
    enc(tm, CU_TENSOR_MAP_DATA_TYPE_FLOAT32, 2, (void*)base, dims, strides, box, es,
        CU_TENSOR_MAP_INTERLEAVE_NONE, CU_TENSOR_MAP_SWIZZLE_128B,
        CU_TENSOR_MAP_L2_PROMOTION_L2_128B, CU_TENSOR_MAP_FLOAT_OOB_FILL_NONE);
}

extern "C" void kernel_launch(void* const* d_in, const int* in_sizes, int n_in,
                              void* d_out, int out_size) {
    const float *z = nullptr, *adj = nullptr, *Ws = nullptr, *bs = nullptr,
                *Wl = nullptr, *bl = nullptr;
    for (int i = 0; i < n_in; i++) {
        switch (in_sizes[i]) {
            case 16384 * 192:  z   = (const float*)d_in[i]; break;
            case 268435456:    adj = (const float*)d_in[i]; break;
            case 8192:         Ws  = (const float*)d_in[i]; break;
            case 128:          bs  = (const float*)d_in[i]; break;
            case 12288:        Wl  = (const float*)d_in[i]; break;
            case 64:           bl  = (const float*)d_in[i]; break;
            default: break;
        }
    }
    float* out = (float*)d_out;

    static EncodeFn enc = nullptr;
    if (!enc) {
        void* p = nullptr;
        cudaDriverEntryPointQueryResult qr;
        cudaGetDriverEntryPointByVersion("cuTensorMapEncodeTiled", &p, 12050,
                                         cudaEnableDefault, &qr);
        enc = (EncodeFn)p;
        cudaFuncSetAttribute(k_big, cudaFuncAttributeMaxDynamicSharedMemorySize, SMEM_TOT);
    }

    void* ttp = nullptr;
    cudaGetSymbolAddress(&ttp, g_Tt);

    CUtensorMap tmA, tmB;
    make_map(enc, &tmA, adj, K_TOT, N_ROWS);   // adj: [16384 m][16384 k]
    make_map(enc, &tmB, ttp, K_TOT, NCOL);     // g_Tt: [128 c][16384 k]

    k_pre<<<dim3(256, 2), 256>>>(z, Ws);
    k_big<<<128, 256, SMEM_TOT>>>(tmA, tmB, bs);
    k_mid<<<dim3(256, 2), 256>>>(Ws + 4096);
    k_big<<<128, 256, SMEM_TOT>>>(tmA, tmB, bs + 64);
    k_final<<<256, 256>>>(z, Wl, bl, out);
}

// round 14
// speedup vs baseline: 1.2583x; 1.2205x over previous
#include <cuda_runtime.h>
#include <cuda.h>
#include <cuda_bf16.h>
#include <cstdint>
#include <cstddef>

#define N_ROWS 16384
#define K_TOT  16384
#define NCOL   128
#define BM     128
#define BK     32
#define KT     (K_TOT / BK)     // 512
#define NSTG   4

// SMEM: A stages (4 x 16KB fp32, SW128) | B stages (4 x 8KB bf16, SW64) | ctrl
#define A_STAGE   16384
#define B_BASE    (NSTG * A_STAGE)          // 65536
#define B_STAGE   8192
#define CTRL_OFF  (B_BASE + NSTG * B_STAGE) // 98304
#define FULL_OFF  (CTRL_OFF)
#define SMEM_TOT  (CTRL_OFF + 64)
#define STAGE_TX  (16384u + 8192u)

__device__ __align__(1024) __nv_bfloat16 g_Tth[(size_t)NCOL * K_TOT]; // B^T bf16: [128 cols][16384 k]
__device__ __align__(1024) float g_Y[(size_t)N_ROWS * NCOL];

__device__ __forceinline__ float elu_f(float x) { return x > 0.0f ? x : expm1f(x); }

__device__ __forceinline__ uint32_t smem_u32(const void* p) {
    uint32_t a;
    asm("{ .reg .u64 t; cvta.to.shared.u64 t, %1; cvt.u32.u64 %0, t; }" : "=r"(a) : "l"(p));
    return a;
}
__device__ __forceinline__ void mbar_init(uint32_t mbar, uint32_t cnt) {
    asm volatile("mbarrier.init.shared.b64 [%0], %1;" :: "r"(mbar), "r"(cnt) : "memory");
}
__device__ __forceinline__ void mbar_expect_tx(uint32_t mbar, uint32_t bytes) {
    asm volatile("mbarrier.arrive.expect_tx.shared.b64 _, [%0], %1;" :: "r"(mbar), "r"(bytes) : "memory");
}
__device__ __forceinline__ void mbar_wait(uint32_t mbar, uint32_t parity) {
    uint32_t done;
    asm volatile(
        "{\n\t.reg .pred p;\n\t"
        "mbarrier.try_wait.parity.acquire.cta.shared::cta.b64 p, [%1], %2;\n\t"
        "selp.b32 %0, 1, 0, p;\n\t}"
        : "=r"(done) : "r"(mbar), "r"(parity) : "memory");
    if (!done) {
        asm volatile(
            "{\n\t.reg .pred P1;\n\t"
            "WL_%=:\n\t"
            "mbarrier.try_wait.parity.acquire.cta.shared::cta.b64 P1, [%0], %1, 0x989680;\n\t"
            "@P1 bra.uni WD_%=;\n\t"
            "bra.uni WL_%=;\n\t"
            "WD_%=:\n\t}"
            :: "r"(mbar), "r"(parity) : "memory");
    }
}
__device__ __forceinline__ void tma2d(uint32_t dst, const CUtensorMap* tm,
                                      int x, int y, uint32_t mbar) {
    asm volatile(
        "cp.async.bulk.tensor.2d.shared::cta.global.tile.mbarrier::complete_tx::bytes "
        "[%0], [%1, {%2, %3}], [%4];"
        :: "r"(dst), "l"(tm), "r"(x), "r"(y), "r"(mbar) : "memory");
}
__device__ __forceinline__ uint32_t cvt_bf16x2(float lo, float hi) {
    uint32_t r;
    asm("cvt.rn.bf16x2.f32 %0, %1, %2;" : "=r"(r) : "f"(hi), "f"(lo));
    return r;
}

// ---------------------------------------------------------------------------
// k_pre: g_Tth[h*64+c][row] = bf16( sum_k elu(z[row, h*64+k]) * W0[k][c] )
// ---------------------------------------------------------------------------
__global__ void k_pre(const float* __restrict__ z, const float* __restrict__ W) {
    int h = blockIdx.y;
    int row0 = blockIdx.x * 64;
    __shared__ float xs[64][65];
    __shared__ float ws[64][65];
    int tid = threadIdx.x;
    for (int i = tid; i < 4096; i += 256) {
        int r = i >> 6, c = i & 63;
        xs[r][c] = elu_f(z[(size_t)(row0 + r) * 192 + h * 64 + c]);
        ws[r][c] = W[r * 64 + c];
    }
    __syncthreads();
    int tr = (tid >> 4) << 2, tc = (tid & 15) << 2;
    float acc[4][4] = {};
#pragma unroll 8
    for (int k = 0; k < 64; k++) {
        float xv[4], wv[4];
#pragma unroll
        for (int i = 0; i < 4; i++) xv[i] = xs[tr + i][k];
#pragma unroll
        for (int j = 0; j < 4; j++) wv[j] = ws[k][tc + j];
#pragma unroll
        for (int i = 0; i < 4; i++)
#pragma unroll
            for (int j = 0; j < 4; j++) acc[i][j] += xv[i] * wv[j];
    }
    __syncthreads();
#pragma unroll
    for (int i = 0; i < 4; i++)
#pragma unroll
        for (int j = 0; j < 4; j++)
            xs[tc + j][tr + i] = acc[i][j];          // transpose in smem
    __syncthreads();
    for (int i = tid; i < 4096; i += 256) {
        int c = i >> 6, r = i & 63;
        g_Tth[(size_t)(h * 64 + c) * K_TOT + row0 + r] = __float2bfloat16_rn(xs[c][r]);
    }
}

// ---------------------------------------------------------------------------
// k_mid: g_Tth[h*64+c][row] = bf16( sum_k Y[row, h*64+k] * W1[k][c] )
// ---------------------------------------------------------------------------
__global__ void k_mid(const float* __restrict__ W) {
    int h = blockIdx.y;
    int row0 = blockIdx.x * 64;
    __shared__ float xs[64][65];
    __shared__ float ws[64][65];
    int tid = threadIdx.x;
    for (int i = tid; i < 4096; i += 256) {
        int r = i >> 6, c = i & 63;
        xs[r][c] = g_Y[(size_t)(row0 + r) * NCOL + h * 64 + c];
        ws[r][c] = W[r * 64 + c];
    }
    __syncthreads();
    int tr = (tid >> 4) << 2, tc = (tid & 15) << 2;
    float acc[4][4] = {};
#pragma unroll 8
    for (int k = 0; k < 64; k++) {
        float xv[4], wv[4];
#pragma unroll
        for (int i = 0; i < 4; i++) xv[i] = xs[tr + i][k];
#pragma unroll
        for (int j = 0; j < 4; j++) wv[j] = ws[k][tc + j];
#pragma unroll
        for (int i = 0; i < 4; i++)
#pragma unroll
            for (int j = 0; j < 4; j++) acc[i][j] += xv[i] * wv[j];
    }
    __syncthreads();
#pragma unroll
    for (int i = 0; i < 4; i++)
#pragma unroll
        for (int j = 0; j < 4; j++)
            xs[tc + j][tr + i] = acc[i][j];
    __syncthreads();
    for (int i = tid; i < 4096; i += 256) {
        int c = i >> 6, r = i & 63;
        g_Tth[(size_t)(h * 64 + c) * K_TOT + row0 + r] = __float2bfloat16_rn(xs[c][r]);
    }
}

// ---------------------------------------------------------------------------
// k_final: out = [Y2_s | Y2_u | z_a] @ Wl + bl
// ---------------------------------------------------------------------------
__global__ void k_final(const float* __restrict__ z, const float* __restrict__ Wl,
                        const float* __restrict__ bl, float* __restrict__ out) {
    int row0 = blockIdx.x * 64;
    __shared__ float xs[64][65];
    __shared__ float ws[64][65];
    int tid = threadIdx.x;
    int tr = (tid >> 4) << 2, tc = (tid & 15) << 2;
    float acc[4][4] = {};
    for (int ch = 0; ch < 3; ch++) {
        __syncthreads();
        for (int i = tid; i < 4096; i += 256) {
            int r = i >> 6, c = i & 63;
            xs[r][c] = (ch < 2) ? g_Y[(size_t)(row0 + r) * NCOL + ch * 64 + c]
                                : z[(size_t)(row0 + r) * 192 + 128 + c];
            ws[r][c] = Wl[(ch * 64 + r) * 64 + c];
        }
        __syncthreads();
#pragma unroll 8
        for (int k = 0; k < 64; k++) {
            float xv[4], wv[4];
#pragma unroll
            for (int i = 0; i < 4; i++) xv[i] = xs[tr + i][k];
#pragma unroll
            for (int j = 0; j < 4; j++) wv[j] = ws[k][tc + j];
#pragma unroll
            for (int i = 0; i < 4; i++)
#pragma unroll
                for (int j = 0; j < 4; j++) acc[i][j] += xv[i] * wv[j];
        }
    }
#pragma unroll
    for (int i = 0; i < 4; i++)
#pragma unroll
        for (int j = 0; j < 4; j++)
            out[(size_t)(row0 + tr + i) * 64 + tc + j] = acc[i][j] + bl[tc + j];
}

// ---------------------------------------------------------------------------
// k_big: Y = elu(adj @ Tth^T + bias)
// A fp32 via TMA SW128 (converted to bf16 in-register); B bf16 via TMA SW64.
// mma.sync m16n8k16 bf16. 256 threads (8 warps, 4M x 2N).
// ---------------------------------------------------------------------------
__global__ void __launch_bounds__(256, 1) k_big(
    const __grid_constant__ CUtensorMap tmA,
    const __grid_constant__ CUtensorMap tmB,
    const float* __restrict__ bias)
{
    extern __shared__ __align__(1024) char smem[];
    uint32_t sb = smem_u32(smem);
    int tid = threadIdx.x;
    int lane = tid & 31, wid = tid >> 5;
    int wm = wid & 3, wn = wid >> 2;                  // 4 M-groups x 2 N-groups
    int m0 = blockIdx.x * BM;

    if (tid == 0) {
#pragma unroll
        for (int s = 0; s < NSTG; s++) mbar_init(sb + FULL_OFF + s * 8, 1);
    }
    __syncthreads();
    if (tid == 0) {
#pragma unroll
        for (int s = 0; s < NSTG; s++) {
            mbar_expect_tx(sb + FULL_OFF + s * 8, STAGE_TX);
            tma2d(sb + s * A_STAGE,          &tmA, s * BK, m0, sb + FULL_OFF + s * 8);
            tma2d(sb + B_BASE + s * B_STAGE, &tmB, s * BK, 0,  sb + FULL_OFF + s * 8);
        }
    }

    float acc[2][8][4];
#pragma unroll
    for (int t = 0; t < 2; t++)
#pragma unroll
        for (int j = 0; j < 8; j++)
#pragma unroll
            for (int q = 0; q < 4; q++) acc[t][j][q] = 0.0f;

    // invariants
    const uint32_t lp4  = (lane & 3);                 // k-pair index
    const uint32_t xorA = ((lane >> 2) & 7) << 4;     // SW128 XOR for A rows
    const int rA = wm * 32 + (lane >> 2);             // A base row (t*16 added)
    const int cB = wn * 64 + (lane >> 2);             // B base col (j*8 added)

    for (int kt = 0; kt < KT; kt++) {
        int s = kt & (NSTG - 1);
        mbar_wait(sb + FULL_OFF + s * 8, (kt >> 2) & 1);
        const char* sa = smem + s * A_STAGE;
        const char* sbb = smem + B_BASE + s * B_STAGE;

#pragma unroll
        for (int ks = 0; ks < 2; ks++) {              // two k16 steps per BK=32
            // A fragments: fp32 LDS.64 pairs -> bf16x2 (RN)
            uint32_t a[2][4];
#pragma unroll
            for (int t = 0; t < 2; t++) {
                uint32_t row0b = (uint32_t)(rA + t * 16) * 128;
                uint32_t row1b = row0b + 8 * 128;
                uint32_t kb0 = (ks * 64 + lp4 * 8) ^ xorA;
                uint32_t kb1 = (ks * 64 + 32 + lp4 * 8) ^ xorA;
                float2 f0 = *(const float2*)(sa + row0b + kb0);
                float2 f1 = *(const float2*)(sa + row1b + kb0);
                float2 f2 = *(const float2*)(sa + row0b + kb1);
                float2 f3 = *(const float2*)(sa + row1b + kb1);
                a[t][0] = cvt_bf16x2(f0.x, f0.y);
                a[t][1] = cvt_bf16x2(f1.x, f1.y);
                a[t][2] = cvt_bf16x2(f2.x, f2.y);
                a[t][3] = cvt_bf16x2(f3.x, f3.y);
            }
#pragma unroll
            for (int j = 0; j < 8; j++) {
                int c = cB + j * 8;
                uint32_t xorB = ((uint32_t)(c & 6)) << 3;  // SW64: unit ^= row bits[1:2]
                uint32_t base = (uint32_t)c * 64 + ks * 32 + lp4 * 4;
                uint32_t b0 = *(const uint32_t*)(sbb + (base ^ xorB));
                uint32_t b1 = *(const uint32_t*)(sbb + ((base + 16) ^ xorB));
#pragma unroll
                for (int t = 0; t < 2; t++) {
                    asm volatile(
                        "mma.sync.aligned.m16n8k16.row.col.f32.bf16.bf16.f32 "
                        "{%0,%1,%2,%3}, {%4,%5,%6,%7}, {%8,%9}, {%0,%1,%2,%3};"
                        : "+f"(acc[t][j][0]), "+f"(acc[t][j][1]),
                          "+f"(acc[t][j][2]), "+f"(acc[t][j][3])
                        : "r"(a[t][0]), "r"(a[t][1]), "r"(a[t][2]), "r"(a[t][3]),
                          "r"(b0), "r"(b1));
                }
            }
        }
        __syncthreads();                              // all warps done with slot s
        int nk = kt + NSTG;
        if (tid == 0 && nk < KT) {
            mbar_expect_tx(sb + FULL_OFF + s * 8, STAGE_TX);
            tma2d(sb + s * A_STAGE,          &tmA, nk * BK, m0, sb + FULL_OFF + s * 8);
            tma2d(sb + B_BASE + s * B_STAGE, &tmB, nk * BK, 0,  sb + FULL_OFF + s * 8);
        }
    }

    // Epilogue: + bias (per-64 broadcast), elu, store fp32
#pragma unroll
    for (int t = 0; t < 2; t++) {
#pragma unroll
        for (int j = 0; j < 8; j++) {
            int r = m0 + wm * 32 + t * 16 + (lane >> 2);
            int c = wn * 64 + j * 8 + ((lane & 3) << 1);
            float b0 = bias[c & 63];
            float b1 = bias[(c + 1) & 63];
            g_Y[(size_t)r * NCOL + c]           = elu_f(acc[t][j][0] + b0);
            g_Y[(size_t)r * NCOL + c + 1]       = elu_f(acc[t][j][1] + b1);
            g_Y[(size_t)(r + 8) * NCOL + c]     = elu_f(acc[t][j][2] + b0);
            g_Y[(size_t)(r + 8) * NCOL + c + 1] = elu_f(acc[t][j][3] + b1);
        }
    }
}

// ---------------------------------------------------------------------------
typedef CUresult (*EncodeFn)(CUtensorMap*, CUtensorMapDataType, cuuint32_t, void*,
                             const cuuint64_t*, const cuuint64_t*, const cuuint32_t*,
                             const cuuint32_t*, CUtensorMapInterleave, CUtensorMapSwizzle,
                             CUtensorMapL2promotion, CUtensorMapFloatOOBfill);

extern "C" void kernel_launch(void* const* d_in, const int* in_sizes, int n_in,
                              void* d_out, int out_size) {
    const float *z = nullptr, *adj = nullptr, *Ws = nullptr, *bs = nullptr,
                *Wl = nullptr, *bl = nullptr;
    for (int i = 0; i < n_in; i++) {
        switch (in_sizes[i]) {
            case 16384 * 192:  z   = (const float*)d_in[i]; break;
            case 268435456:    adj = (const float*)d_in[i]; break;
            case 8192:         Ws  = (const float*)d_in[i]; break;
            case 128:          bs  = (const float*)d_in[i]; break;
            case 12288:        Wl  = (const float*)d_in[i]; break;
            case 64:           bl  = (const float*)d_in[i]; break;
            default: break;
        }
    }
    float* out = (float*)d_out;

    static EncodeFn enc = nullptr;
    if (!enc) {
        void* p = nullptr;
        cudaDriverEntryPointQueryResult qr;
        cudaGetDriverEntryPointByVersion("cuTensorMapEncodeTiled", &p, 12050,
                                         cudaEnableDefault, &qr);
        enc = (EncodeFn)p;
        cudaFuncSetAttribute(k_big, cudaFuncAttributeMaxDynamicSharedMemorySize, SMEM_TOT);
    }

    void* ttp = nullptr;
    cudaGetSymbolAddress(&ttp, g_Tth);

    // A: fp32 [16384 m][16384 k], box 32x128, SW128
    CUtensorMap tmA;
    {
        cuuint64_t dims[2] = {K_TOT, N_ROWS};
        cuuint64_t strides[1] = {K_TOT * 4};
        cuuint32_t box[2] = {32, 128};
        cuuint32_t es[2] = {1, 1};
        enc(&tmA, CU_TENSOR_MAP_DATA_TYPE_FLOAT32, 2, (void*)adj, dims, strides, box, es,
            CU_TENSOR_MAP_INTERLEAVE_NONE, CU_TENSOR_MAP_SWIZZLE_128B,
            CU_TENSOR_MAP_L2_PROMOTION_L2_128B, CU_TENSOR_MAP_FLOAT_OOB_FILL_NONE);
    }
    // B: bf16 [128 c][16384 k], box 32x128 (64B rows), SW64
    CUtensorMap tmB;
    {
        cuuint64_t dims[2] = {K_TOT, NCOL};
        cuuint64_t strides[1] = {K_TOT * 2};
        cuuint32_t box[2] = {32, 128};
        cuuint32_t es[2] = {1, 1};
        enc(&tmB, CU_TENSOR_MAP_DATA_TYPE_BFLOAT16, 2, ttp, dims, strides, box, es,
            CU_TENSOR_MAP_INTERLEAVE_NONE, CU_TENSOR_MAP_SWIZZLE_64B,
            CU_TENSOR_MAP_L2_PROMOTION_L2_128B, CU_TENSOR_MAP_FLOAT_OOB_FILL_NONE);
    }

    k_pre<<<dim3(256, 2), 256>>>(z, Ws);
    k_big<<<128, 256, SMEM_TOT>>>(tmA, tmB, bs);
    k_mid<<<dim3(256, 2), 256>>>(Ws + 4096);
    k_big<<<128, 256, SMEM_TOT>>>(tmA, tmB, bs + 64);
    k_final<<<256, 256>>>(z, Wl, bl, out);
}

// round 16
// speedup vs baseline: 1.5783x; 1.2543x over previous
#include <cuda_runtime.h>
#include <cuda.h>
#include <cuda_bf16.h>
#include <cstdint>
#include <cstddef>

#define N_ROWS 16384
#define K_TOT  16384
#define K_HALF 8192
#define NCOL   128
#define BM     128
#define BK     32
#define KT_H   (K_HALF / BK)    // 256 ktiles per CTA
#define NSTG   4

// SMEM: A stages (4 x 16KB fp32, SW128) | B stages (4 x 8KB bf16, SW64) | ctrl
#define A_STAGE   16384
#define B_BASE    (NSTG * A_STAGE)          // 65536
#define B_STAGE   8192
#define CTRL_OFF  (B_BASE + NSTG * B_STAGE) // 98304
#define FULL_OFF  (CTRL_OFF)
#define SMEM_TOT  (CTRL_OFF + 64)
#define STAGE_TX  (16384u + 8192u)

__device__ __align__(1024) __nv_bfloat16 g_Tth[(size_t)NCOL * K_TOT]; // B^T bf16
__device__ __align__(1024) float g_P[2][(size_t)N_ROWS * NCOL];       // split-K partials
__device__ __align__(1024) float g_Y[(size_t)N_ROWS * NCOL];

__device__ __forceinline__ float elu_f(float x) { return x > 0.0f ? x : expm1f(x); }

__device__ __forceinline__ uint32_t smem_u32(const void* p) {
    uint32_t a;
    asm("{ .reg .u64 t; cvta.to.shared.u64 t, %1; cvt.u32.u64 %0, t; }" : "=r"(a) : "l"(p));
    return a;
}
__device__ __forceinline__ void mbar_init(uint32_t mbar, uint32_t cnt) {
    asm volatile("mbarrier.init.shared.b64 [%0], %1;" :: "r"(mbar), "r"(cnt) : "memory");
}
__device__ __forceinline__ void mbar_expect_tx(uint32_t mbar, uint32_t bytes) {
    asm volatile("mbarrier.arrive.expect_tx.shared.b64 _, [%0], %1;" :: "r"(mbar), "r"(bytes) : "memory");
}
__device__ __forceinline__ void mbar_wait(uint32_t mbar, uint32_t parity) {
    uint32_t done;
    asm volatile(
        "{\n\t.reg .pred p;\n\t"
        "mbarrier.try_wait.parity.acquire.cta.shared::cta.b64 p, [%1], %2;\n\t"
        "selp.b32 %0, 1, 0, p;\n\t}"
        : "=r"(done) : "r"(mbar), "r"(parity) : "memory");
    if (!done) {
        asm volatile(
            "{\n\t.reg .pred P1;\n\t"
            "WL_%=:\n\t"
            "mbarrier.try_wait.parity.acquire.cta.shared::cta.b64 P1, [%0], %1, 0x989680;\n\t"
            "@P1 bra.uni WD_%=;\n\t"
            "bra.uni WL_%=;\n\t"
            "WD_%=:\n\t}"
            :: "r"(mbar), "r"(parity) : "memory");
    }
}
__device__ __forceinline__ void tma2d(uint32_t dst, const CUtensorMap* tm,
                                      int x, int y, uint32_t mbar) {
    asm volatile(
        "cp.async.bulk.tensor.2d.shared::cta.global.tile.mbarrier::complete_tx::bytes "
        "[%0], [%1, {%2, %3}], [%4];"
        :: "r"(dst), "l"(tm), "r"(x), "r"(y), "r"(mbar) : "memory");
}
__device__ __forceinline__ uint32_t cvt_bf16x2(float lo, float hi) {
    uint32_t r;
    asm("cvt.rn.bf16x2.f32 %0, %1, %2;" : "=r"(r) : "f"(hi), "f"(lo));
    return r;
}

// ---------------------------------------------------------------------------
// k_pre: g_Tth[h*64+c][row] = bf16( sum_k elu(z[row, h*64+k]) * W0[k][c] )
// ---------------------------------------------------------------------------
__global__ void k_pre(const float* __restrict__ z, const float* __restrict__ W) {
    int h = blockIdx.y;
    int row0 = blockIdx.x * 64;
    __shared__ float xs[64][65];
    __shared__ float ws[64][65];
    int tid = threadIdx.x;
    for (int i = tid; i < 4096; i += 256) {
        int r = i >> 6, c = i & 63;
        xs[r][c] = elu_f(z[(size_t)(row0 + r) * 192 + h * 64 + c]);
        ws[r][c] = W[r * 64 + c];
    }
    __syncthreads();
    int tr = (tid >> 4) << 2, tc = (tid & 15) << 2;
    float acc[4][4] = {};
#pragma unroll 8
    for (int k = 0; k < 64; k++) {
        float xv[4], wv[4];
#pragma unroll
        for (int i = 0; i < 4; i++) xv[i] = xs[tr + i][k];
#pragma unroll
        for (int j = 0; j < 4; j++) wv[j] = ws[k][tc + j];
#pragma unroll
        for (int i = 0; i < 4; i++)
#pragma unroll
            for (int j = 0; j < 4; j++) acc[i][j] += xv[i] * wv[j];
    }
    __syncthreads();
#pragma unroll
    for (int i = 0; i < 4; i++)
#pragma unroll
        for (int j = 0; j < 4; j++)
            xs[tc + j][tr + i] = acc[i][j];          // transpose in smem
    __syncthreads();
    for (int i = tid; i < 4096; i += 256) {
        int c = i >> 6, r = i & 63;
        g_Tth[(size_t)(h * 64 + c) * K_TOT + row0 + r] = __float2bfloat16_rn(xs[c][r]);
    }
}

// ---------------------------------------------------------------------------
// k_mid: g_Tth[h*64+c][row] = bf16( sum_k Y[row, h*64+k] * W1[k][c] )
// ---------------------------------------------------------------------------
__global__ void k_mid(const float* __restrict__ W) {
    int h = blockIdx.y;
    int row0 = blockIdx.x * 64;
    __shared__ float xs[64][65];
    __shared__ float ws[64][65];
    int tid = threadIdx.x;
    for (int i = tid; i < 4096; i += 256) {
        int r = i >> 6, c = i & 63;
        xs[r][c] = g_Y[(size_t)(row0 + r) * NCOL + h * 64 + c];
        ws[r][c] = W[r * 64 + c];
    }
    __syncthreads();
    int tr = (tid >> 4) << 2, tc = (tid & 15) << 2;
    float acc[4][4] = {};
#pragma unroll 8
    for (int k = 0; k < 64; k++) {
        float xv[4], wv[4];
#pragma unroll
        for (int i = 0; i < 4; i++) xv[i] = xs[tr + i][k];
#pragma unroll
        for (int j = 0; j < 4; j++) wv[j] = ws[k][tc + j];
#pragma unroll
        for (int i = 0; i < 4; i++)
#pragma unroll
            for (int j = 0; j < 4; j++) acc[i][j] += xv[i] * wv[j];
    }
    __syncthreads();
#pragma unroll
    for (int i = 0; i < 4; i++)
#pragma unroll
        for (int j = 0; j < 4; j++)
            xs[tc + j][tr + i] = acc[i][j];
    __syncthreads();
    for (int i = tid; i < 4096; i += 256) {
        int c = i >> 6, r = i & 63;
        g_Tth[(size_t)(h * 64 + c) * K_TOT + row0 + r] = __float2bfloat16_rn(xs[c][r]);
    }
}

// ---------------------------------------------------------------------------
// k_comb: g_Y = elu(P0 + P1 + bias)   (vectorized float4)
// ---------------------------------------------------------------------------
__global__ void k_comb(const float* __restrict__ bias) {
    size_t i = ((size_t)blockIdx.x * 256 + threadIdx.x) * 4;
    float4 p0 = *(const float4*)&g_P[0][i];
    float4 p1 = *(const float4*)&g_P[1][i];
    int c = (int)(i & 127) & 63;
    float4 r;
    r.x = elu_f(p0.x + p1.x + bias[c]);
    r.y = elu_f(p0.y + p1.y + bias[c + 1]);
    r.z = elu_f(p0.z + p1.z + bias[c + 2]);
    r.w = elu_f(p0.w + p1.w + bias[c + 3]);
    *(float4*)&g_Y[i] = r;
}

// ---------------------------------------------------------------------------
// k_final: out = [Y2_s | Y2_u | z_a] @ Wl + bl
// ---------------------------------------------------------------------------
__global__ void k_final(const float* __restrict__ z, const float* __restrict__ Wl,
                        const float* __restrict__ bl, float* __restrict__ out) {
    int row0 = blockIdx.x * 64;
    __shared__ float xs[64][65];
    __shared__ float ws[64][65];
    int tid = threadIdx.x;
    int tr = (tid >> 4) << 2, tc = (tid & 15) << 2;
    float acc[4][4] = {};
    for (int ch = 0; ch < 3; ch++) {
        __syncthreads();
        for (int i = tid; i < 4096; i += 256) {
            int r = i >> 6, c = i & 63;
            xs[r][c] = (ch < 2) ? g_Y[(size_t)(row0 + r) * NCOL + ch * 64 + c]
                                : z[(size_t)(row0 + r) * 192 + 128 + c];
            ws[r][c] = Wl[(ch * 64 + r) * 64 + c];
        }
        __syncthreads();
#pragma unroll 8
        for (int k = 0; k < 64; k++) {
            float xv[4], wv[4];
#pragma unroll
            for (int i = 0; i < 4; i++) xv[i] = xs[tr + i][k];
#pragma unroll
            for (int j = 0; j < 4; j++) wv[j] = ws[k][tc + j];
#pragma unroll
            for (int i = 0; i < 4; i++)
#pragma unroll
                for (int j = 0; j < 4; j++) acc[i][j] += xv[i] * wv[j];
        }
    }
#pragma unroll
    for (int i = 0; i < 4; i++)
#pragma unroll
        for (int j = 0; j < 4; j++)
            out[(size_t)(row0 + tr + i) * 64 + tc + j] = acc[i][j] + bl[tc + j];
}

// ---------------------------------------------------------------------------
// k_big: split-K partial P[half][m0:m0+128][:] = adj[m0:,kh] @ Tth[:,kh]^T
// grid 256: half = bx>>7, m-block = bx&127. Target 2 CTAs/SM (16 warps).
// A fp32 TMA SW128 -> bf16 in-register; B bf16 TMA SW64; mma m16n8k16.
// ---------------------------------------------------------------------------
__global__ void __launch_bounds__(256, 2) k_big(
    const __grid_constant__ CUtensorMap tmA,
    const __grid_constant__ CUtensorMap tmB)
{
    extern __shared__ __align__(1024) char smem[];
    uint32_t sb = smem_u32(smem);
    int tid = threadIdx.x;
    int lane = tid & 31, wid = tid >> 5;
    int wm = wid & 3, wn = wid >> 2;                  // 4 M-groups x 2 N-groups
    int half = blockIdx.x >> 7;
    int m0 = (blockIdx.x & 127) * BM;
    int kbase = half * K_HALF;

    if (tid == 0) {
#pragma unroll
        for (int s = 0; s < NSTG; s++) mbar_init(sb + FULL_OFF + s * 8, 1);
    }
    __syncthreads();
    if (tid == 0) {
#pragma unroll
        for (int s = 0; s < NSTG; s++) {
            mbar_expect_tx(sb + FULL_OFF + s * 8, STAGE_TX);
            tma2d(sb + s * A_STAGE,          &tmA, kbase + s * BK, m0, sb + FULL_OFF + s * 8);
            tma2d(sb + B_BASE + s * B_STAGE, &tmB, kbase + s * BK, 0,  sb + FULL_OFF + s * 8);
        }
    }

    float acc[2][8][4];
#pragma unroll
    for (int t = 0; t < 2; t++)
#pragma unroll
        for (int j = 0; j < 8; j++)
#pragma unroll
            for (int q = 0; q < 4; q++) acc[t][j][q] = 0.0f;

    const uint32_t lp4  = (lane & 3);
    const uint32_t xorA = ((lane >> 2) & 7) << 4;
    const int rA = wm * 32 + (lane >> 2);
    const int cB = wn * 64 + (lane >> 2);

    for (int kt = 0; kt < KT_H; kt++) {
        int s = kt & (NSTG - 1);
        mbar_wait(sb + FULL_OFF + s * 8, (kt >> 2) & 1);
        const char* sa = smem + s * A_STAGE;
        const char* sbb = smem + B_BASE + s * B_STAGE;

#pragma unroll
        for (int ks = 0; ks < 2; ks++) {
            uint32_t a[2][4];
#pragma unroll
            for (int t = 0; t < 2; t++) {
                uint32_t row0b = (uint32_t)(rA + t * 16) * 128;
                uint32_t row1b = row0b + 8 * 128;
                uint32_t kb0 = (ks * 64 + lp4 * 8) ^ xorA;
                uint32_t kb1 = (ks * 64 + 32 + lp4 * 8) ^ xorA;
                float2 f0 = *(const float2*)(sa + row0b + kb0);
                float2 f1 = *(const float2*)(sa + row1b + kb0);
                float2 f2 = *(const float2*)(sa + row0b + kb1);
                float2 f3 = *(const float2*)(sa + row1b + kb1);
                a[t][0] = cvt_bf16x2(f0.x, f0.y);
                a[t][1] = cvt_bf16x2(f1.x, f1.y);
                a[t][2] = cvt_bf16x2(f2.x, f2.y);
                a[t][3] = cvt_bf16x2(f3.x, f3.y);
            }
#pragma unroll
            for (int j = 0; j < 8; j++) {
                int c = cB + j * 8;
                uint32_t xorB = ((uint32_t)(c & 6)) << 3;
                uint32_t base = (uint32_t)c * 64 + ks * 32 + lp4 * 4;
                uint32_t b0 = *(const uint32_t*)(sbb + (base ^ xorB));
                uint32_t b1 = *(const uint32_t*)(sbb + ((base + 16) ^ xorB));
#pragma unroll
                for (int t = 0; t < 2; t++) {
                    asm volatile(
                        "mma.sync.aligned.m16n8k16.row.col.f32.bf16.bf16.f32 "
                        "{%0,%1,%2,%3}, {%4,%5,%6,%7}, {%8,%9}, {%0,%1,%2,%3};"
                        : "+f"(acc[t][j][0]), "+f"(acc[t][j][1]),
                          "+f"(acc[t][j][2]), "+f"(acc[t][j][3])
                        : "r"(a[t][0]), "r"(a[t][1]), "r"(a[t][2]), "r"(a[t][3]),
                          "r"(b0), "r"(b1));
                }
            }
        }
        __syncthreads();
        int nk = kt + NSTG;
        if (tid == 0 && nk < KT_H) {
            mbar_expect_tx(sb + FULL_OFF + s * 8, STAGE_TX);
            tma2d(sb + s * A_STAGE,          &tmA, kbase + nk * BK, m0, sb + FULL_OFF + s * 8);
            tma2d(sb + B_BASE + s * B_STAGE, &tmB, kbase + nk * BK, 0,  sb + FULL_OFF + s * 8);
        }
    }

    // Epilogue: store raw partial
    float* P = g_P[half];
#pragma unroll
    for (int t = 0; t < 2; t++) {
#pragma unroll
        for (int j = 0; j < 8; j++) {
            int r = m0 + wm * 32 + t * 16 + (lane >> 2);
            int c = wn * 64 + j * 8 + ((lane & 3) << 1);
            P[(size_t)r * NCOL + c]           = acc[t][j][0];
            P[(size_t)r * NCOL + c + 1]       = acc[t][j][1];
            P[(size_t)(r + 8) * NCOL + c]     = acc[t][j][2];
            P[(size_t)(r + 8) * NCOL + c + 1] = acc[t][j][3];
        }
    }
}

// ---------------------------------------------------------------------------
typedef CUresult (*EncodeFn)(CUtensorMap*, CUtensorMapDataType, cuuint32_t, void*,
                             const cuuint64_t*, const cuuint64_t*, const cuuint32_t*,
                             const cuuint32_t*, CUtensorMapInterleave, CUtensorMapSwizzle,
                             CUtensorMapL2promotion, CUtensorMapFloatOOBfill);

extern "C" void kernel_launch(void* const* d_in, const int* in_sizes, int n_in,
                              void* d_out, int out_size) {
    const float *z = nullptr, *adj = nullptr, *Ws = nullptr, *bs = nullptr,
                *Wl = nullptr, *bl = nullptr;
    for (int i = 0; i < n_in; i++) {
        switch (in_sizes[i]) {
            case 16384 * 192:  z   = (const float*)d_in[i]; break;
            case 268435456:    adj = (const float*)d_in[i]; break;
            case 8192:         Ws  = (const float*)d_in[i]; break;
            case 128:          bs  = (const float*)d_in[i]; break;
            case 12288:        Wl  = (const float*)d_in[i]; break;
            case 64:           bl  = (const float*)d_in[i]; break;
            default: break;
        }
    }
    float* out = (float*)d_out;

    static EncodeFn enc = nullptr;
    if (!enc) {
        void* p = nullptr;
        cudaDriverEntryPointQueryResult qr;
        cudaGetDriverEntryPointByVersion("cuTensorMapEncodeTiled", &p, 12050,
                                         cudaEnableDefault, &qr);
        enc = (EncodeFn)p;
        cudaFuncSetAttribute(k_big, cudaFuncAttributeMaxDynamicSharedMemorySize, SMEM_TOT);
    }

    void* ttp = nullptr;
    cudaGetSymbolAddress(&ttp, g_Tth);

    CUtensorMap tmA;
    {
        cuuint64_t dims[2] = {K_TOT, N_ROWS};
        cuuint64_t strides[1] = {K_TOT * 4};
        cuuint32_t box[2] = {32, 128};
        cuuint32_t es[2] = {1, 1};
        enc(&tmA, CU_TENSOR_MAP_DATA_TYPE_FLOAT32, 2, (void*)adj, dims, strides, box, es,
            CU_TENSOR_MAP_INTERLEAVE_NONE, CU_TENSOR_MAP_SWIZZLE_128B,
            CU_TENSOR_MAP_L2_PROMOTION_L2_128B, CU_TENSOR_MAP_FLOAT_OOB_FILL_NONE);
    }
    CUtensorMap tmB;
    {
        cuuint64_t dims[2] = {K_TOT, NCOL};
        cuuint64_t strides[1] = {K_TOT * 2};
        cuuint32_t box[2] = {32, 128};
        cuuint32_t es[2] = {1, 1};
        enc(&tmB, CU_TENSOR_MAP_DATA_TYPE_BFLOAT16, 2, ttp, dims, strides, box, es,
            CU_TENSOR_MAP_INTERLEAVE_NONE, CU_TENSOR_MAP_SWIZZLE_64B,
            CU_TENSOR_MAP_L2_PROMOTION_L2_128B, CU_TENSOR_MAP_FLOAT_OOB_FILL_NONE);
    }

    k_pre<<<dim3(256, 2), 256>>>(z, Ws);
    k_big<<<256, 256, SMEM_TOT>>>(tmA, tmB);
    k_comb<<<2048, 256>>>(bs);
    k_mid<<<dim3(256, 2), 256>>>(Ws + 4096);
    k_big<<<256, 256, SMEM_TOT>>>(tmA, tmB);
    k_comb<<<2048, 256>>>(bs + 64);
    k_final<<<256, 256>>>(z, Wl, bl, out);
}